// round 6
// baseline (speedup 1.0000x reference)
#include <cuda_runtime.h>
#include <cuda_bf16.h>
#include <math.h>
#include <cstdint>

// ---------------- problem constants ----------------
#define HH 8
#define BB 8
#define LL 2048
#define MM 1024
#define DD 64
#define NPH 16384                         // tokens per head = BB*LL

// output layout (fp32, reference return order)
#define OFF_ZQ   0
#define N_ZQ     (8*512*2048)             // 8,388,608
#define OFF_LOSS (N_ZQ)
#define OFF_IDX  (N_ZQ + 1)
#define OFF_CB   (OFF_IDX + BB*HH*LL)

#define RMS_EPS  1.1920929e-07f
#define COS_EPS  1e-8f

// ---------------- device scratch (no allocs) ----------------
__device__ __align__(128) __nv_bfloat16 g_c1[HH*MM*DD];
__device__ __align__(128) __nv_bfloat16 g_c2[HH*MM*DD];
__device__ __align__(128) __nv_bfloat16 g_c3[HH*MM*DD];
__device__ __align__(16) float g_sums[HH*MM*DD];
__device__ float g_counts[HH*MM];
__device__ float g_loss;

// ---------------- mma / ldmatrix / cp.async helpers ----------------
__device__ __forceinline__ void mma_bf16(float* d, const uint32_t* a,
                                         const uint32_t* b) {
    asm volatile(
        "mma.sync.aligned.m16n8k16.row.col.f32.bf16.bf16.f32 "
        "{%0,%1,%2,%3}, {%4,%5,%6,%7}, {%8,%9}, {%0,%1,%2,%3};"
        : "+f"(d[0]), "+f"(d[1]), "+f"(d[2]), "+f"(d[3])
        : "r"(a[0]), "r"(a[1]), "r"(a[2]), "r"(a[3]), "r"(b[0]), "r"(b[1]));
}
__device__ __forceinline__ void ldsm_x4(uint32_t& r0, uint32_t& r1,
                                        uint32_t& r2, uint32_t& r3,
                                        uint32_t addr) {
    asm volatile("ldmatrix.sync.aligned.m8n8.x4.shared.b16 {%0,%1,%2,%3}, [%4];"
                 : "=r"(r0), "=r"(r1), "=r"(r2), "=r"(r3) : "r"(addr));
}
__device__ __forceinline__ uint32_t smem_u32(const void* p) {
    uint32_t a;
    asm("{ .reg .u64 t; cvta.to.shared.u64 t, %1; cvt.u32.u64 %0, t; }"
        : "=r"(a) : "l"(p));
    return a;
}
#define CP16(dst, src) \
    asm volatile("cp.async.cg.shared.global [%0], [%1], 16;" \
                 :: "r"(dst), "l"(src))
#define CP_COMMIT() asm volatile("cp.async.commit_group;" ::: "memory")
#define CP_WAIT(n)  asm volatile("cp.async.wait_group %0;" :: "n"(n) : "memory")

// ---------------- split fp32 -> 3 bf16 terms ----------------
__device__ __forceinline__ void split3(float v, __nv_bfloat16& a, __nv_bfloat16& b,
                                       __nv_bfloat16& c) {
    a = __float2bfloat16(v);
    float r = v - __bfloat162float(a);
    b = __float2bfloat16(r);
    float r2 = r - __bfloat162float(b);
    c = __float2bfloat16(r2);
}
__device__ __forceinline__ uint32_t pack2(__nv_bfloat16 lo, __nv_bfloat16 hi) {
    __nv_bfloat162 t;
    t.x = lo; t.y = hi;
    return *(uint32_t*)&t;
}

// ---------------------------------------------------------------------------
// K0: prep — split codebooks to 3 bf16 terms; zero scratch
// ---------------------------------------------------------------------------
__global__ __launch_bounds__(256)
void vq_prep(const float* __restrict__ cb) {
    int i = blockIdx.x * 256 + threadIdx.x;   // < 524288
    float v = cb[i];
    __nv_bfloat16 a, b, c;
    split3(v, a, b, c);
    g_c1[i] = a; g_c2[i] = b; g_c3[i] = c;
    g_sums[i] = 0.0f;
    if (i < HH * MM) g_counts[i] = 0.0f;
    if (i == 0) g_loss = 0.0f;
}

// ---------------------------------------------------------------------------
// K1: fused — z stage + split + HMMA 6-pair sim-GEMM + argmax + epilogue
// CTA = (head, 256 tokens). 8 warps; warp w owns rows [w*32, w*32+32).
// B double-buffered via cp.async.
// ---------------------------------------------------------------------------
#define BPITCH 144
#define BTERM  (128 * BPITCH)             // 18432 B / term
#define BSTAGE (3 * BTERM)                // 55296 B / stage
#define ZPITCH 260
#define SM_Z    (2 * BSTAGE)              // 110592
#define SM_SIDX (SM_Z + 64 * ZPITCH * 4)  // 177152
#define SM_WSUM (SM_SIDX + 1024)          // 178176
#define SM_TOTAL (SM_WSUM + 32)           // 178208

__global__ __launch_bounds__(256, 1)
void vq_gemm(const float* __restrict__ z, const float* __restrict__ cb,
             float* __restrict__ out) {
    extern __shared__ char smem[];
    float* zsh = (float*)(smem + SM_Z);
    int* sidx = (int*)(smem + SM_SIDX);
    float* wsum = (float*)(smem + SM_WSUM);
    const uint32_t sb = smem_u32(smem);

    const int h  = blockIdx.y;
    const int n0 = blockIdx.x * 256;
    const int b  = n0 >> 11;              // batch
    const int l0 = n0 & 2047;             // l offset within batch
    const int tid = threadIdx.x;
    const int w = tid >> 5, l = tid & 31;
    const int gq = l >> 2, tq = l & 3;

    // ---- prologue: cp.async stage z (fp32) and B tile 0 ----
    const float* zb = z + ((size_t)b * 512 + (size_t)h * 64) * 2048 + l0;
    for (int i = tid; i < 64 * 64; i += 256) {       // 64 k x 64 uint4
        int k = i >> 6, c = i & 63;
        CP16(sb + SM_Z + (k * ZPITCH + c * 4) * 4,
             (const char*)(zb + (size_t)k * 2048 + c * 4));
    }
#pragma unroll
    for (int t3 = 0; t3 < 3; t3++) {
        const __nv_bfloat16* cp = (t3 == 0) ? g_c1 : (t3 == 1) ? g_c2 : g_c3;
        const char* src = (const char*)(cp + (size_t)h * MM * DD);
        for (int i = tid; i < 1024; i += 256) {
            int r = i >> 3, c = i & 7;
            CP16(sb + t3 * BTERM + r * BPITCH + c * 16, src + i * 16);
        }
    }
    CP_COMMIT();
    CP_WAIT(0);
    __syncthreads();

    // ---- build A fragments: 3 terms x 4 ksteps x 2 rowblocks x 4 regs ----
    uint32_t afr[3][4][2][4];
    {
        const int r0 = w * 32 + gq;
#pragma unroll
        for (int ks = 0; ks < 4; ks++)
#pragma unroll
            for (int half = 0; half < 2; half++)
#pragma unroll
                for (int rb = 0; rb < 2; rb++)
#pragma unroll
                    for (int rr = 0; rr < 2; rr++) {
                        int k0 = ks * 16 + 2 * tq + half * 8;
                        int row = r0 + rb * 16 + rr * 8;
                        float v0 = zsh[k0 * ZPITCH + row];
                        float v1 = zsh[(k0 + 1) * ZPITCH + row];
                        __nv_bfloat16 a0, b0, c0, a1, b1, c1;
                        split3(v0, a0, b0, c0);
                        split3(v1, a1, b1, c1);
                        int reg = rr + half * 2;
                        afr[0][ks][rb][reg] = pack2(a0, a1);
                        afr[1][ks][rb][reg] = pack2(b0, b1);
                        afr[2][ks][rb][reg] = pack2(c0, c1);
                    }
    }

    float best[4] = {-3.0e38f, -3.0e38f, -3.0e38f, -3.0e38f};
    int   bidx[4] = {0, 0, 0, 0};

    const int PA[6] = {0, 0, 1, 0, 1, 2};
    const int PB[6] = {0, 1, 0, 2, 1, 0};

    const uint32_t laneoff = (((l >> 4) * 8 + (l & 7)) * BPITCH) +
                             (((l >> 3) & 1) * 16);

    for (int mt = 0; mt < 8; mt++) {
        // prefetch next B tile into the other stage
        if (mt < 7) {
            uint32_t dstb = sb + ((mt + 1) & 1) * BSTAGE;
#pragma unroll
            for (int t3 = 0; t3 < 3; t3++) {
                const __nv_bfloat16* cp = (t3 == 0) ? g_c1 : (t3 == 1) ? g_c2 : g_c3;
                const char* src =
                    (const char*)(cp + ((size_t)h * MM + (mt + 1) * 128) * DD);
                for (int i = tid; i < 1024; i += 256) {
                    int r = i >> 3, c = i & 7;
                    CP16(dstb + t3 * BTERM + r * BPITCH + c * 16, src + i * 16);
                }
            }
            CP_COMMIT();
            CP_WAIT(1);
        } else {
            CP_WAIT(0);
        }
        __syncthreads();

        const uint32_t bbase = sb + (mt & 1) * BSTAGE + laneoff;

#pragma unroll
        for (int sg = 0; sg < 4; sg++) {
            float acc[2][4][4];
#pragma unroll
            for (int rb = 0; rb < 2; rb++)
#pragma unroll
                for (int s = 0; s < 4; s++)
#pragma unroll
                    for (int i = 0; i < 4; i++) acc[rb][s][i] = 0.0f;

#pragma unroll
            for (int ks = 0; ks < 4; ks++) {
                uint32_t bfr[3][4][2];
#pragma unroll
                for (int t3 = 0; t3 < 3; t3++)
#pragma unroll
                    for (int sp = 0; sp < 2; sp++) {
                        uint32_t addr = bbase + t3 * BTERM +
                                        (sg * 32 + sp * 16) * BPITCH + ks * 32;
                        ldsm_x4(bfr[t3][sp * 2][0], bfr[t3][sp * 2][1],
                                bfr[t3][sp * 2 + 1][0], bfr[t3][sp * 2 + 1][1],
                                addr);
                    }
#pragma unroll
                for (int p6 = 0; p6 < 6; p6++)
#pragma unroll
                    for (int rb = 0; rb < 2; rb++)
#pragma unroll
                        for (int s = 0; s < 4; s++)
                            mma_bf16(acc[rb][s], afr[PA[p6]][ks][rb],
                                     bfr[PB[p6]][s]);
            }

            // argmax update (ascending scan, strict > keeps lowest index)
#pragma unroll
            for (int rb = 0; rb < 2; rb++)
#pragma unroll
                for (int s = 0; s < 4; s++) {
                    int nb = mt * 128 + sg * 32 + s * 8 + 2 * tq;
                    if (acc[rb][s][0] > best[2*rb]) { best[2*rb] = acc[rb][s][0]; bidx[2*rb] = nb; }
                    if (acc[rb][s][1] > best[2*rb]) { best[2*rb] = acc[rb][s][1]; bidx[2*rb] = nb + 1; }
                    if (acc[rb][s][2] > best[2*rb+1]) { best[2*rb+1] = acc[rb][s][2]; bidx[2*rb+1] = nb; }
                    if (acc[rb][s][3] > best[2*rb+1]) { best[2*rb+1] = acc[rb][s][3]; bidx[2*rb+1] = nb + 1; }
                }
        }
        __syncthreads();
    }

    // ---- reduce argmax across the 4 lanes covering each row ----
#pragma unroll
    for (int off = 1; off <= 2; off <<= 1)
#pragma unroll
        for (int q = 0; q < 4; q++) {
            float ov = __shfl_xor_sync(0xFFFFFFFFu, best[q], off);
            int   oi = __shfl_xor_sync(0xFFFFFFFFu, bidx[q], off);
            if (ov > best[q] || (ov == best[q] && oi < bidx[q])) {
                best[q] = ov; bidx[q] = oi;
            }
        }

    if (tq == 0) {
#pragma unroll
        for (int q = 0; q < 4; q++) {
            int rl = w * 32 + (q >> 1) * 16 + (q & 1) * 8 + gq;
            sidx[rl] = bidx[q];
            out[OFF_IDX + ((size_t)(b * HH + h)) * LL + l0 + rl] = (float)bidx[q];
            atomicAdd(&g_counts[h * MM + bidx[q]], 1.0f);
        }
    }
    __syncthreads();

    // ---- fused epilogue: z_q write, loss, segment sums ----
    const float* cbh = cb + (size_t)h * MM * DD;
    float* zqb = out + OFF_ZQ + ((size_t)b * 512 + (size_t)h * 64) * 2048 + l0;
    float lsum = 0.0f;
    for (int i = tid; i < 64 * 256; i += 256) {
        int k = i >> 8, ll = i & 255;
        int m = sidx[ll];
        float cv = __ldg(&cbh[(size_t)m * DD + k]);
        float zv = zsh[k * ZPITCH + ll];
        float d = zv - cv;
        lsum += d * d;
        zqb[(size_t)k * 2048 + ll] = cv;
    }

    // segment sums: thread = (l, 4k-group) -> float4 atomic
    for (int i = tid; i < 256 * 16; i += 256) {
        int ll = i >> 4, kg = i & 15;
        int m = sidx[ll];
        float4 v = make_float4(zsh[(4 * kg) * ZPITCH + ll],
                               zsh[(4 * kg + 1) * ZPITCH + ll],
                               zsh[(4 * kg + 2) * ZPITCH + ll],
                               zsh[(4 * kg + 3) * ZPITCH + ll]);
        atomicAdd((float4*)&g_sums[((size_t)(h * MM + m)) * DD + 4 * kg], v);
    }

    // loss reduce
#pragma unroll
    for (int off = 16; off > 0; off >>= 1)
        lsum += __shfl_xor_sync(0xFFFFFFFFu, lsum, off);
    if (l == 0) wsum[w] = lsum;
    __syncthreads();
    if (tid == 0) {
        float s = 0.0f;
#pragma unroll
        for (int ww = 0; ww < 8; ww++) s += wsum[ww];
        atomicAdd(&g_loss, s);
    }
}

// ---------------------------------------------------------------------------
// K2: EMA slerp codebook update + loss finalize. One warp per (h, m).
// ---------------------------------------------------------------------------
__global__ __launch_bounds__(256)
void vq_update(const float* __restrict__ cb, float* __restrict__ out) {
    int gid = blockIdx.x * blockDim.x + threadIdx.x;
    int gw = gid >> 5;
    int lane = threadIdx.x & 31;

    if (gw == 0 && lane == 0)
        out[OFF_LOSS] = 1.25f * g_loss / 8388608.0f;

    if (gw >= HH * MM) return;
    int h = gw >> 10;
    int m = gw & (MM - 1);

    const float* hi = cb + ((size_t)h * MM + m) * DD;
    float h0 = hi[lane], h1 = hi[lane + 32];
    float cnt = g_counts[h * MM + m];
    float o0 = h0, o1 = h1;

    if (cnt > 0.0f) {
        float inv = 1.0f / fmaxf(cnt, 1.0f);
        const float* sp = g_sums + ((size_t)h * MM + m) * DD;
        float s0 = sp[lane] * inv, s1 = sp[lane + 32] * inv;

        float dot = s0 * h0 + s1 * h1;
        float nl = s0 * s0 + s1 * s1;
        float nh = h0 * h0 + h1 * h1;
#pragma unroll
        for (int off = 16; off > 0; off >>= 1) {
            dot += __shfl_xor_sync(0xFFFFFFFFu, dot, off);
            nl  += __shfl_xor_sync(0xFFFFFFFFu, nl, off);
            nh  += __shfl_xor_sync(0xFFFFFFFFu, nh, off);
        }
        float c = dot / fmaxf(sqrtf(nl) * sqrtf(nh), COS_EPS);
        c = fminf(fmaxf(c, -1.0f + 1e-7f), 1.0f - 1e-7f);
        float om = acosf(c);
        float so = sinf(om);
        float wl = sinf(0.01f * om) / so;
        float wh = sinf(0.99f * om) / so;
        float r0 = s0 * wl + h0 * wh;
        float r1 = s1 * wl + h1 * wh;

        float ms = r0 * r0 + r1 * r1;
#pragma unroll
        for (int off = 16; off > 0; off >>= 1)
            ms += __shfl_xor_sync(0xFFFFFFFFu, ms, off);
        float rinv = rsqrtf(ms * (1.0f / 64.0f) + RMS_EPS);
        o0 = r0 * rinv;
        o1 = r1 * rinv;
    }

    size_t ob = OFF_CB + ((size_t)h * MM + m) * DD;
    out[ob + lane] = o0;
    out[ob + lane + 32] = o1;
}

// ---------------------------------------------------------------------------
extern "C" void kernel_launch(void* const* d_in, const int* in_sizes, int n_in,
                              void* d_out, int out_size) {
    const float* z  = (const float*)d_in[0];
    const float* cb = (const float*)d_in[1];
    float* out = (float*)d_out;

    cudaFuncSetAttribute(vq_gemm, cudaFuncAttributeMaxDynamicSharedMemorySize,
                         SM_TOTAL);

    vq_prep<<<2048, 256>>>(cb);
    vq_gemm<<<dim3(64, 8), 256, SM_TOTAL>>>(z, cb, out);
    vq_update<<<1024, 256>>>(cb, out);
}

// round 7
// speedup vs baseline: 1.2003x; 1.2003x over previous
#include <cuda_runtime.h>
#include <cuda_bf16.h>
#include <math.h>
#include <cstdint>

// ---------------- problem constants ----------------
#define HH 8
#define BB 8
#define LL 2048
#define MM 1024
#define DD 64
#define NPH 16384                         // tokens per head = BB*LL

// output layout (fp32, reference return order)
#define OFF_ZQ   0
#define N_ZQ     (8*512*2048)             // 8,388,608
#define OFF_LOSS (N_ZQ)
#define OFF_IDX  (N_ZQ + 1)
#define OFF_CB   (OFF_IDX + BB*HH*LL)

#define RMS_EPS  1.1920929e-07f
#define COS_EPS  1e-8f

// ---------------- device scratch (no allocs) ----------------
__device__ __align__(128) __nv_bfloat16 g_c1[HH*MM*DD];
__device__ __align__(128) __nv_bfloat16 g_c2[HH*MM*DD];
__device__ __align__(128) __nv_bfloat16 g_c3[HH*MM*DD];
__device__ __align__(16) float g_sums[HH*MM*DD];
__device__ float g_counts[HH*MM];
__device__ float g_loss;

// ---------------- mma / ldmatrix / cp.async helpers ----------------
__device__ __forceinline__ void mma_bf16(float* d, const uint32_t* a,
                                         const uint32_t* b) {
    asm volatile(
        "mma.sync.aligned.m16n8k16.row.col.f32.bf16.bf16.f32 "
        "{%0,%1,%2,%3}, {%4,%5,%6,%7}, {%8,%9}, {%0,%1,%2,%3};"
        : "+f"(d[0]), "+f"(d[1]), "+f"(d[2]), "+f"(d[3])
        : "r"(a[0]), "r"(a[1]), "r"(a[2]), "r"(a[3]), "r"(b[0]), "r"(b[1]));
}
__device__ __forceinline__ void ldsm_x4(uint32_t& r0, uint32_t& r1,
                                        uint32_t& r2, uint32_t& r3,
                                        uint32_t addr) {
    asm volatile("ldmatrix.sync.aligned.m8n8.x4.shared.b16 {%0,%1,%2,%3}, [%4];"
                 : "=r"(r0), "=r"(r1), "=r"(r2), "=r"(r3) : "r"(addr));
}
__device__ __forceinline__ uint32_t smem_u32(const void* p) {
    uint32_t a;
    asm("{ .reg .u64 t; cvta.to.shared.u64 t, %1; cvt.u32.u64 %0, t; }"
        : "=r"(a) : "l"(p));
    return a;
}
#define CP16(dst, src) \
    asm volatile("cp.async.cg.shared.global [%0], [%1], 16;" \
                 :: "r"(dst), "l"(src))
#define CP_COMMIT() asm volatile("cp.async.commit_group;" ::: "memory")
#define CP_WAIT(n)  asm volatile("cp.async.wait_group %0;" :: "n"(n) : "memory")

// ---------------- split fp32 -> 3 bf16 terms ----------------
__device__ __forceinline__ void split3(float v, __nv_bfloat16& a, __nv_bfloat16& b,
                                       __nv_bfloat16& c) {
    a = __float2bfloat16(v);
    float r = v - __bfloat162float(a);
    b = __float2bfloat16(r);
    float r2 = r - __bfloat162float(b);
    c = __float2bfloat16(r2);
}
__device__ __forceinline__ uint32_t pack2(__nv_bfloat16 lo, __nv_bfloat16 hi) {
    __nv_bfloat162 t;
    t.x = lo; t.y = hi;
    return *(uint32_t*)&t;
}

// ---------------------------------------------------------------------------
// K0: prep — split codebooks to 3 bf16 terms; zero scratch
// ---------------------------------------------------------------------------
__global__ __launch_bounds__(256)
void vq_prep(const float* __restrict__ cb) {
    int i = blockIdx.x * 256 + threadIdx.x;   // < 524288
    float v = cb[i];
    __nv_bfloat16 a, b, c;
    split3(v, a, b, c);
    g_c1[i] = a; g_c2[i] = b; g_c3[i] = c;
    g_sums[i] = 0.0f;
    if (i < HH * MM) g_counts[i] = 0.0f;
    if (i == 0) g_loss = 0.0f;
}

// ---------------------------------------------------------------------------
// K1: fused — z stage + split + HMMA 6-pair sim-GEMM + argmax + epilogue
// CTA = (head, 128 tokens). 8 warps; warp w owns rows [w*16, w*16+16).
// B staged in 64-code tiles, cp.async double-buffered (16 tiles).
// ---------------------------------------------------------------------------
#define BPITCH 144
#define BT64   (64 * BPITCH)              // 9216 B per term per stage
#define BSTAGE (3 * BT64)                 // 27648 B per stage
#define ZPITCH 132
#define SM_Z    (2 * BSTAGE)              // 55296
#define SM_SIDX (SM_Z + 64 * ZPITCH * 4)  // 89088
#define SM_WSUM (SM_SIDX + 512)           // 89600
#define SM_TOTAL (SM_WSUM + 32)           // 89632  -> 2 CTAs/SM

__global__ __launch_bounds__(256, 2)
void vq_gemm(const float* __restrict__ z, const float* __restrict__ cb,
             float* __restrict__ out) {
    extern __shared__ char smem[];
    float* zsh = (float*)(smem + SM_Z);
    int* sidx = (int*)(smem + SM_SIDX);
    float* wsum = (float*)(smem + SM_WSUM);
    const uint32_t sb = smem_u32(smem);

    const int h  = blockIdx.y;
    const int n0 = blockIdx.x * 128;
    const int b  = n0 >> 11;              // batch
    const int l0 = n0 & 2047;             // l offset within batch
    const int tid = threadIdx.x;
    const int w = tid >> 5, l = tid & 31;
    const int gq = l >> 2, tq = l & 3;

    // ---- prologue: cp.async z tile (group Z), then B tile 0 (group 0) ----
    const float* zb = z + ((size_t)b * 512 + (size_t)h * 64) * 2048 + l0;
    for (int i = tid; i < 64 * 32; i += 256) {
        int k = i >> 5, c = i & 31;
        CP16(sb + SM_Z + (k * ZPITCH + c * 4) * 4,
             (const char*)(zb + (size_t)k * 2048 + c * 4));
    }
    CP_COMMIT();
    {   // B tile 0 -> stage 0
        for (int j = tid; j < 1536; j += 256) {
            int t3 = j >> 9, rr = (j >> 3) & 63, c = j & 7;
            const __nv_bfloat16* cp = (t3 == 0) ? g_c1 : (t3 == 1) ? g_c2 : g_c3;
            CP16(sb + t3 * BT64 + rr * BPITCH + c * 16,
                 (const char*)(cp + ((size_t)h * MM + rr) * DD) + c * 16);
        }
    }
    CP_COMMIT();

    CP_WAIT(1);              // z ready (B tile 0 may still be in flight)
    __syncthreads();

    // ---- build A fragments in regs: 3 terms x 4 ksteps x 4 regs ----
    uint32_t afr[3][4][4];
    {
        const int r0 = w * 16 + gq;
#pragma unroll
        for (int ks = 0; ks < 4; ks++)
#pragma unroll
            for (int half = 0; half < 2; half++)
#pragma unroll
                for (int rr = 0; rr < 2; rr++) {
                    int k0 = ks * 16 + 2 * tq + half * 8;
                    int row = r0 + rr * 8;
                    float v0 = zsh[k0 * ZPITCH + row];
                    float v1 = zsh[(k0 + 1) * ZPITCH + row];
                    __nv_bfloat16 a0, b0, c0, a1, b1, c1;
                    split3(v0, a0, b0, c0);
                    split3(v1, a1, b1, c1);
                    int reg = rr + half * 2;
                    afr[0][ks][reg] = pack2(a0, a1);
                    afr[1][ks][reg] = pack2(b0, b1);
                    afr[2][ks][reg] = pack2(c0, c1);
                }
    }

    float best0 = -3.0e38f, best1 = -3.0e38f;
    int   bidx0 = 0, bidx1 = 0;

    const int PA[6] = {0, 0, 1, 0, 1, 2};
    const int PB[6] = {0, 1, 0, 2, 1, 0};

    const uint32_t laneoff = (((l >> 4) * 8 + (l & 7)) * BPITCH) +
                             (((l >> 3) & 1) * 16);

    for (int mt = 0; mt < 16; mt++) {
        CP_WAIT(0);                        // tile mt resident in stage mt&1
        __syncthreads();                   // all warps done with prior stage use

        if (mt < 15) {                     // prefetch tile mt+1 into other stage
            uint32_t dstb = sb + ((mt + 1) & 1) * BSTAGE;
            for (int j = tid; j < 1536; j += 256) {
                int t3 = j >> 9, rr = (j >> 3) & 63, c = j & 7;
                const __nv_bfloat16* cp =
                    (t3 == 0) ? g_c1 : (t3 == 1) ? g_c2 : g_c3;
                CP16(dstb + t3 * BT64 + rr * BPITCH + c * 16,
                     (const char*)(cp + ((size_t)h * MM + (mt + 1) * 64 + rr) * DD)
                         + c * 16);
            }
            CP_COMMIT();
        }

        const uint32_t bbase = sb + (mt & 1) * BSTAGE + laneoff;

#pragma unroll
        for (int sg = 0; sg < 2; sg++) {
            float acc[4][4];
#pragma unroll
            for (int s = 0; s < 4; s++)
#pragma unroll
                for (int i = 0; i < 4; i++) acc[s][i] = 0.0f;

#pragma unroll
            for (int ks = 0; ks < 4; ks++) {
                uint32_t bfr[3][4][2];
#pragma unroll
                for (int t3 = 0; t3 < 3; t3++)
#pragma unroll
                    for (int sp = 0; sp < 2; sp++) {
                        uint32_t addr = bbase + t3 * BT64 +
                                        (sg * 32 + sp * 16) * BPITCH + ks * 32;
                        ldsm_x4(bfr[t3][sp * 2][0], bfr[t3][sp * 2][1],
                                bfr[t3][sp * 2 + 1][0], bfr[t3][sp * 2 + 1][1],
                                addr);
                    }
#pragma unroll
                for (int p6 = 0; p6 < 6; p6++)
#pragma unroll
                    for (int s = 0; s < 4; s++)
                        mma_bf16(acc[s], afr[PA[p6]][ks], bfr[PB[p6]][s]);
            }

            // argmax update (ascending scan, strict > keeps lowest index)
#pragma unroll
            for (int s = 0; s < 4; s++) {
                int nb = mt * 64 + sg * 32 + s * 8 + 2 * tq;
                if (acc[s][0] > best0) { best0 = acc[s][0]; bidx0 = nb; }
                if (acc[s][1] > best0) { best0 = acc[s][1]; bidx0 = nb + 1; }
                if (acc[s][2] > best1) { best1 = acc[s][2]; bidx1 = nb; }
                if (acc[s][3] > best1) { best1 = acc[s][3]; bidx1 = nb + 1; }
            }
        }
    }

    // ---- reduce argmax across the 4 lanes covering each row ----
#pragma unroll
    for (int off = 1; off <= 2; off <<= 1) {
        float ov = __shfl_xor_sync(0xFFFFFFFFu, best0, off);
        int   oi = __shfl_xor_sync(0xFFFFFFFFu, bidx0, off);
        if (ov > best0 || (ov == best0 && oi < bidx0)) { best0 = ov; bidx0 = oi; }
        ov = __shfl_xor_sync(0xFFFFFFFFu, best1, off);
        oi = __shfl_xor_sync(0xFFFFFFFFu, bidx1, off);
        if (ov > best1 || (ov == best1 && oi < bidx1)) { best1 = ov; bidx1 = oi; }
    }

    if (tq == 0) {
        int rl = w * 16 + gq;
        sidx[rl] = bidx0;
        sidx[rl + 8] = bidx1;
        out[OFF_IDX + ((size_t)(b * HH + h)) * LL + l0 + rl] = (float)bidx0;
        out[OFF_IDX + ((size_t)(b * HH + h)) * LL + l0 + rl + 8] = (float)bidx1;
        atomicAdd(&g_counts[h * MM + bidx0], 1.0f);
        atomicAdd(&g_counts[h * MM + bidx1], 1.0f);
    }
    __syncthreads();

    // ---- fused epilogue: z_q write, loss, segment sums ----
    const float* cbh = cb + (size_t)h * MM * DD;
    float* zqb = out + OFF_ZQ + ((size_t)b * 512 + (size_t)h * 64) * 2048 + l0;
    float lsum = 0.0f;
    for (int i = tid; i < 64 * 128; i += 256) {
        int k = i >> 7, ll = i & 127;
        int m = sidx[ll];
        float cv = __ldg(&cbh[(size_t)m * DD + k]);
        float zv = zsh[k * ZPITCH + ll];
        float d = zv - cv;
        lsum += d * d;
        zqb[(size_t)k * 2048 + ll] = cv;
    }

    // segment sums: thread = (l, 4k-group) -> float4 atomic
    for (int i = tid; i < 128 * 16; i += 256) {
        int ll = i >> 4, kg = i & 15;
        int m = sidx[ll];
        float4 v = make_float4(zsh[(4 * kg) * ZPITCH + ll],
                               zsh[(4 * kg + 1) * ZPITCH + ll],
                               zsh[(4 * kg + 2) * ZPITCH + ll],
                               zsh[(4 * kg + 3) * ZPITCH + ll]);
        atomicAdd((float4*)&g_sums[((size_t)(h * MM + m)) * DD + 4 * kg], v);
    }

    // loss reduce
#pragma unroll
    for (int off = 16; off > 0; off >>= 1)
        lsum += __shfl_xor_sync(0xFFFFFFFFu, lsum, off);
    if (l == 0) wsum[w] = lsum;
    __syncthreads();
    if (tid == 0) {
        float s = 0.0f;
#pragma unroll
        for (int ww = 0; ww < 8; ww++) s += wsum[ww];
        atomicAdd(&g_loss, s);
    }
}

// ---------------------------------------------------------------------------
// K2: EMA slerp codebook update + loss finalize. One warp per (h, m).
// ---------------------------------------------------------------------------
__global__ __launch_bounds__(256)
void vq_update(const float* __restrict__ cb, float* __restrict__ out) {
    int gid = blockIdx.x * blockDim.x + threadIdx.x;
    int gw = gid >> 5;
    int lane = threadIdx.x & 31;

    if (gw == 0 && lane == 0)
        out[OFF_LOSS] = 1.25f * g_loss / 8388608.0f;

    if (gw >= HH * MM) return;
    int h = gw >> 10;
    int m = gw & (MM - 1);

    const float* hi = cb + ((size_t)h * MM + m) * DD;
    float h0 = hi[lane], h1 = hi[lane + 32];
    float cnt = g_counts[h * MM + m];
    float o0 = h0, o1 = h1;

    if (cnt > 0.0f) {
        float inv = 1.0f / fmaxf(cnt, 1.0f);
        const float* sp = g_sums + ((size_t)h * MM + m) * DD;
        float s0 = sp[lane] * inv, s1 = sp[lane + 32] * inv;

        float dot = s0 * h0 + s1 * h1;
        float nl = s0 * s0 + s1 * s1;
        float nh = h0 * h0 + h1 * h1;
#pragma unroll
        for (int off = 16; off > 0; off >>= 1) {
            dot += __shfl_xor_sync(0xFFFFFFFFu, dot, off);
            nl  += __shfl_xor_sync(0xFFFFFFFFu, nl, off);
            nh  += __shfl_xor_sync(0xFFFFFFFFu, nh, off);
        }
        float c = dot / fmaxf(sqrtf(nl) * sqrtf(nh), COS_EPS);
        c = fminf(fmaxf(c, -1.0f + 1e-7f), 1.0f - 1e-7f);
        float om = acosf(c);
        float so = sinf(om);
        float wl = sinf(0.01f * om) / so;
        float wh = sinf(0.99f * om) / so;
        float r0 = s0 * wl + h0 * wh;
        float r1 = s1 * wl + h1 * wh;

        float ms = r0 * r0 + r1 * r1;
#pragma unroll
        for (int off = 16; off > 0; off >>= 1)
            ms += __shfl_xor_sync(0xFFFFFFFFu, ms, off);
        float rinv = rsqrtf(ms * (1.0f / 64.0f) + RMS_EPS);
        o0 = r0 * rinv;
        o1 = r1 * rinv;
    }

    size_t ob = OFF_CB + ((size_t)h * MM + m) * DD;
    out[ob + lane] = o0;
    out[ob + lane + 32] = o1;
}

// ---------------------------------------------------------------------------
extern "C" void kernel_launch(void* const* d_in, const int* in_sizes, int n_in,
                              void* d_out, int out_size) {
    const float* z  = (const float*)d_in[0];
    const float* cb = (const float*)d_in[1];
    float* out = (float*)d_out;

    cudaFuncSetAttribute(vq_gemm, cudaFuncAttributeMaxDynamicSharedMemorySize,
                         SM_TOTAL);

    vq_prep<<<2048, 256>>>(cb);
    vq_gemm<<<dim3(128, 8), 256, SM_TOTAL>>>(z, cb, out);
    vq_update<<<1024, 256>>>(cb, out);
}

// round 8
// speedup vs baseline: 1.3405x; 1.1168x over previous
#include <cuda_runtime.h>
#include <cuda_bf16.h>
#include <math.h>
#include <cstdint>

// ---------------- problem constants ----------------
#define HH 8
#define BB 8
#define LL 2048
#define MM 1024
#define DD 64
#define NPH 16384                         // tokens per head = BB*LL

// output layout (fp32, reference return order)
#define OFF_ZQ   0
#define N_ZQ     (8*512*2048)             // 8,388,608
#define OFF_LOSS (N_ZQ)
#define OFF_IDX  (N_ZQ + 1)
#define OFF_CB   (OFF_IDX + BB*HH*LL)

#define RMS_EPS  1.1920929e-07f
#define COS_EPS  1e-8f

// ---------------- device scratch (no allocs) ----------------
__device__ __align__(128) __nv_bfloat16 g_c1[HH*MM*DD];
__device__ __align__(128) __nv_bfloat16 g_c2[HH*MM*DD];
__device__ __align__(16) float g_sums[HH*MM*DD];
__device__ float g_counts[HH*MM];
__device__ float g_loss;

// ---------------- mma / ldmatrix / cp.async helpers ----------------
__device__ __forceinline__ void mma_bf16(float* d, const uint32_t* a,
                                         const uint32_t* b) {
    asm volatile(
        "mma.sync.aligned.m16n8k16.row.col.f32.bf16.bf16.f32 "
        "{%0,%1,%2,%3}, {%4,%5,%6,%7}, {%8,%9}, {%0,%1,%2,%3};"
        : "+f"(d[0]), "+f"(d[1]), "+f"(d[2]), "+f"(d[3])
        : "r"(a[0]), "r"(a[1]), "r"(a[2]), "r"(a[3]), "r"(b[0]), "r"(b[1]));
}
__device__ __forceinline__ void ldsm_x4(uint32_t& r0, uint32_t& r1,
                                        uint32_t& r2, uint32_t& r3,
                                        uint32_t addr) {
    asm volatile("ldmatrix.sync.aligned.m8n8.x4.shared.b16 {%0,%1,%2,%3}, [%4];"
                 : "=r"(r0), "=r"(r1), "=r"(r2), "=r"(r3) : "r"(addr));
}
__device__ __forceinline__ uint32_t smem_u32(const void* p) {
    uint32_t a;
    asm("{ .reg .u64 t; cvta.to.shared.u64 t, %1; cvt.u32.u64 %0, t; }"
        : "=r"(a) : "l"(p));
    return a;
}
#define CP16(dst, src) \
    asm volatile("cp.async.cg.shared.global [%0], [%1], 16;" \
                 :: "r"(dst), "l"(src))
#define CP_COMMIT() asm volatile("cp.async.commit_group;" ::: "memory")
#define CP_WAIT(n)  asm volatile("cp.async.wait_group %0;" :: "n"(n) : "memory")

// ---------------- split fp32 -> 2 bf16 terms ----------------
__device__ __forceinline__ void split2(float v, __nv_bfloat16& a,
                                       __nv_bfloat16& b) {
    a = __float2bfloat16(v);
    b = __float2bfloat16(v - __bfloat162float(a));
}
__device__ __forceinline__ uint32_t pack2(__nv_bfloat16 lo, __nv_bfloat16 hi) {
    __nv_bfloat162 t;
    t.x = lo; t.y = hi;
    return *(uint32_t*)&t;
}

// top-2 helpers
__device__ __forceinline__ void upd2(float& b1, int& i1, float& b2, int& i2,
                                     float v, int idx) {
    if (v > b1) { b2 = b1; i2 = i1; b1 = v; i1 = idx; }
    else if (v > b2) { b2 = v; i2 = idx; }
}
__device__ __forceinline__ bool better(float av, int ai, float bv, int bi) {
    return av > bv || (av == bv && ai < bi);
}
__device__ __forceinline__ void merge2(float& b1, int& i1, float& b2, int& i2,
                                       float o1, int oi1, float o2, int oi2) {
    if (better(o1, oi1, b1, i1)) {
        if (better(b1, i1, o2, oi2)) { b2 = b1; i2 = i1; }
        else { b2 = o2; i2 = oi2; }
        b1 = o1; i1 = oi1;
    } else if (better(o1, oi1, b2, i2)) {
        b2 = o1; i2 = oi1;
    }
}

// ---------------------------------------------------------------------------
// K0: prep — split codebooks to 2 bf16 terms; zero scratch
// ---------------------------------------------------------------------------
__global__ __launch_bounds__(256)
void vq_prep(const float* __restrict__ cb) {
    int i = blockIdx.x * 256 + threadIdx.x;   // < 524288
    float v = cb[i];
    __nv_bfloat16 a, b;
    split2(v, a, b);
    g_c1[i] = a; g_c2[i] = b;
    g_sums[i] = 0.0f;
    if (i < HH * MM) g_counts[i] = 0.0f;
    if (i == 0) g_loss = 0.0f;
}

// dummy launch to align the profiler's fixed capture slot onto vq_gemm
__global__ void vq_nop() {}

// ---------------------------------------------------------------------------
// K1: fused — z stage + split + 3-pair HMMA phase-1 + top-2 + exact rescore
//     + epilogue. CTA = (head, 128 tokens). 8 warps, 16 rows each.
// ---------------------------------------------------------------------------
#define BPITCH 144
#define BT64   (64 * BPITCH)              // 9216 B per term per stage
#define BSTAGE (2 * BT64)                 // 18432 B per stage (2 terms)
#define ZPITCH 132
#define SM_Z     (2 * BSTAGE)             // 36864
#define SM_CANDS (SM_Z + 64 * ZPITCH * 4) // 70656
#define SM_SIDX  (SM_CANDS + 1024)        // 71680
#define SM_WSUM  (SM_SIDX + 512)          // 72192
#define SM_TOTAL (SM_WSUM + 32)           // 72224  -> 2 CTAs/SM

__global__ __launch_bounds__(256, 2)
void vq_gemm(const float* __restrict__ z, const float* __restrict__ cb,
             float* __restrict__ out) {
    extern __shared__ char smem[];
    float* zsh = (float*)(smem + SM_Z);
    int2* cands = (int2*)(smem + SM_CANDS);
    int* sidx = (int*)(smem + SM_SIDX);
    float* wsum = (float*)(smem + SM_WSUM);
    const uint32_t sb = smem_u32(smem);

    const int h  = blockIdx.y;
    const int n0 = blockIdx.x * 128;
    const int b  = n0 >> 11;              // batch
    const int l0 = n0 & 2047;             // l offset within batch
    const int tid = threadIdx.x;
    const int w = tid >> 5, l = tid & 31;
    const int gq = l >> 2, tq = l & 3;

    // ---- prologue: cp.async z tile (group Z), then B tile 0 (group 0) ----
    const float* zb = z + ((size_t)b * 512 + (size_t)h * 64) * 2048 + l0;
    for (int i = tid; i < 64 * 32; i += 256) {
        int k = i >> 5, c = i & 31;
        CP16(sb + SM_Z + (k * ZPITCH + c * 4) * 4,
             (const char*)(zb + (size_t)k * 2048 + c * 4));
    }
    CP_COMMIT();
    for (int j = tid; j < 1024; j += 256) {     // B tile 0 -> stage 0
        int t3 = j >> 9, rr = (j >> 3) & 63, c = j & 7;
        const __nv_bfloat16* cp = t3 ? g_c2 : g_c1;
        CP16(sb + t3 * BT64 + rr * BPITCH + c * 16,
             (const char*)(cp + ((size_t)h * MM + rr) * DD) + c * 16);
    }
    CP_COMMIT();

    CP_WAIT(1);              // z ready (B tile 0 may still be in flight)
    __syncthreads();

    // ---- build A fragments in regs: 2 terms x 4 ksteps x 4 regs ----
    uint32_t afr[2][4][4];
    {
        const int r0 = w * 16 + gq;
#pragma unroll
        for (int ks = 0; ks < 4; ks++)
#pragma unroll
            for (int half = 0; half < 2; half++)
#pragma unroll
                for (int rr = 0; rr < 2; rr++) {
                    int k0 = ks * 16 + 2 * tq + half * 8;
                    int row = r0 + rr * 8;
                    float v0 = zsh[k0 * ZPITCH + row];
                    float v1 = zsh[(k0 + 1) * ZPITCH + row];
                    __nv_bfloat16 a0, b0, a1, b1;
                    split2(v0, a0, b0);
                    split2(v1, a1, b1);
                    int reg = rr + half * 2;
                    afr[0][ks][reg] = pack2(a0, a1);
                    afr[1][ks][reg] = pack2(b0, b1);
                }
    }

    // per-thread top-2 for the two row outputs (row rl and rl+8)
    float b0a = -3.0e38f, b0b = -3.0e38f, b1a = -3.0e38f, b1b = -3.0e38f;
    int   i0a = 0, i0b = 1, i1a = 0, i1b = 1;

    const uint32_t laneoff = (((l >> 4) * 8 + (l & 7)) * BPITCH) +
                             (((l >> 3) & 1) * 16);

    for (int mt = 0; mt < 16; mt++) {
        CP_WAIT(0);                        // tile mt resident in stage mt&1
        __syncthreads();

        if (mt < 15) {                     // prefetch tile mt+1 into other stage
            uint32_t dstb = sb + ((mt + 1) & 1) * BSTAGE;
            for (int j = tid; j < 1024; j += 256) {
                int t3 = j >> 9, rr = (j >> 3) & 63, c = j & 7;
                const __nv_bfloat16* cp = t3 ? g_c2 : g_c1;
                CP16(dstb + t3 * BT64 + rr * BPITCH + c * 16,
                     (const char*)(cp + ((size_t)h * MM + (mt + 1) * 64 + rr) * DD)
                         + c * 16);
            }
            CP_COMMIT();
        }

        const uint32_t bbase = sb + (mt & 1) * BSTAGE + laneoff;

#pragma unroll
        for (int sg = 0; sg < 2; sg++) {
            float acc[4][4];
#pragma unroll
            for (int s = 0; s < 4; s++)
#pragma unroll
                for (int i = 0; i < 4; i++) acc[s][i] = 0.0f;

#pragma unroll
            for (int ks = 0; ks < 4; ks++) {
                uint32_t bfr[2][4][2];
#pragma unroll
                for (int t3 = 0; t3 < 2; t3++)
#pragma unroll
                    for (int sp = 0; sp < 2; sp++) {
                        uint32_t addr = bbase + t3 * BT64 +
                                        (sg * 32 + sp * 16) * BPITCH + ks * 32;
                        ldsm_x4(bfr[t3][sp * 2][0], bfr[t3][sp * 2][1],
                                bfr[t3][sp * 2 + 1][0], bfr[t3][sp * 2 + 1][1],
                                addr);
                    }
                // 3 pairs: (z1,c1), (z1,c2), (z2,c1)
#pragma unroll
                for (int s = 0; s < 4; s++) {
                    mma_bf16(acc[s], afr[0][ks], bfr[0][s]);
                    mma_bf16(acc[s], afr[0][ks], bfr[1][s]);
                    mma_bf16(acc[s], afr[1][ks], bfr[0][s]);
                }
            }

            // top-2 update (ascending index scan, strict > keeps lowest)
#pragma unroll
            for (int s = 0; s < 4; s++) {
                int nb = mt * 64 + sg * 32 + s * 8 + 2 * tq;
                upd2(b0a, i0a, b0b, i0b, acc[s][0], nb);
                upd2(b0a, i0a, b0b, i0b, acc[s][1], nb + 1);
                upd2(b1a, i1a, b1b, i1b, acc[s][2], nb);
                upd2(b1a, i1a, b1b, i1b, acc[s][3], nb + 1);
            }
        }
    }

    // ---- merge top-2 across the 4 lanes covering each row ----
#pragma unroll
    for (int off = 1; off <= 2; off <<= 1) {
        float o1 = __shfl_xor_sync(0xFFFFFFFFu, b0a, off);
        int   q1 = __shfl_xor_sync(0xFFFFFFFFu, i0a, off);
        float o2 = __shfl_xor_sync(0xFFFFFFFFu, b0b, off);
        int   q2 = __shfl_xor_sync(0xFFFFFFFFu, i0b, off);
        merge2(b0a, i0a, b0b, i0b, o1, q1, o2, q2);
        o1 = __shfl_xor_sync(0xFFFFFFFFu, b1a, off);
        q1 = __shfl_xor_sync(0xFFFFFFFFu, i1a, off);
        o2 = __shfl_xor_sync(0xFFFFFFFFu, b1b, off);
        q2 = __shfl_xor_sync(0xFFFFFFFFu, i1b, off);
        merge2(b1a, i1a, b1b, i1b, o1, q1, o2, q2);
    }

    if (tq == 0) {
        int rl = w * 16 + gq;
        cands[rl] = make_int2(i0a, i0b);
        cands[rl + 8] = make_int2(i1a, i1b);
    }
    __syncthreads();

    // ---- exact fp32 rescore of the 2 candidates per row ----
    const float* cbh = cb + (size_t)h * MM * DD;
    {
        int row = tid >> 1, c = tid & 1;
        int2 cc = cands[row];
        int m = c ? cc.y : cc.x;
        const float4* cr = (const float4*)(cbh + (size_t)m * DD);
        float dot = 0.0f;
#pragma unroll
        for (int k4 = 0; k4 < 16; k4++) {
            float4 cv = __ldg(cr + k4);
            dot += zsh[(4 * k4) * ZPITCH + row] * cv.x;
            dot += zsh[(4 * k4 + 1) * ZPITCH + row] * cv.y;
            dot += zsh[(4 * k4 + 2) * ZPITCH + row] * cv.z;
            dot += zsh[(4 * k4 + 3) * ZPITCH + row] * cv.w;
        }
        float od = __shfl_xor_sync(0xFFFFFFFFu, dot, 1);
        int   om = __shfl_xor_sync(0xFFFFFFFFu, m, 1);
        if (c == 0) {
            int win = better(dot, m, od, om) ? m : om;
            sidx[row] = win;
            out[OFF_IDX + ((size_t)(b * HH + h)) * LL + l0 + row] = (float)win;
            atomicAdd(&g_counts[h * MM + win], 1.0f);
        }
    }
    __syncthreads();

    // ---- fused epilogue: z_q write, loss, segment sums ----
    float* zqb = out + OFF_ZQ + ((size_t)b * 512 + (size_t)h * 64) * 2048 + l0;
    float lsum = 0.0f;
    for (int i = tid; i < 64 * 128; i += 256) {
        int k = i >> 7, ll = i & 127;
        int m = sidx[ll];
        float cv = __ldg(&cbh[(size_t)m * DD + k]);
        float zv = zsh[k * ZPITCH + ll];
        float d = zv - cv;
        lsum += d * d;
        zqb[(size_t)k * 2048 + ll] = cv;
    }

    // segment sums: thread = (l, 4k-group) -> float4 atomic
    for (int i = tid; i < 128 * 16; i += 256) {
        int ll = i >> 4, kg = i & 15;
        int m = sidx[ll];
        float4 v = make_float4(zsh[(4 * kg) * ZPITCH + ll],
                               zsh[(4 * kg + 1) * ZPITCH + ll],
                               zsh[(4 * kg + 2) * ZPITCH + ll],
                               zsh[(4 * kg + 3) * ZPITCH + ll]);
        atomicAdd((float4*)&g_sums[((size_t)(h * MM + m)) * DD + 4 * kg], v);
    }

    // loss reduce
#pragma unroll
    for (int off = 16; off > 0; off >>= 1)
        lsum += __shfl_xor_sync(0xFFFFFFFFu, lsum, off);
    if (l == 0) wsum[w] = lsum;
    __syncthreads();
    if (tid == 0) {
        float s = 0.0f;
#pragma unroll
        for (int ww = 0; ww < 8; ww++) s += wsum[ww];
        atomicAdd(&g_loss, s);
    }
}

// ---------------------------------------------------------------------------
// K2: EMA slerp codebook update + loss finalize. One warp per (h, m).
// ---------------------------------------------------------------------------
__global__ __launch_bounds__(256)
void vq_update(const float* __restrict__ cb, float* __restrict__ out) {
    int gid = blockIdx.x * blockDim.x + threadIdx.x;
    int gw = gid >> 5;
    int lane = threadIdx.x & 31;

    if (gw == 0 && lane == 0)
        out[OFF_LOSS] = 1.25f * g_loss / 8388608.0f;

    if (gw >= HH * MM) return;
    int h = gw >> 10;
    int m = gw & (MM - 1);

    const float* hi = cb + ((size_t)h * MM + m) * DD;
    float h0 = hi[lane], h1 = hi[lane + 32];
    float cnt = g_counts[h * MM + m];
    float o0 = h0, o1 = h1;

    if (cnt > 0.0f) {
        float inv = 1.0f / fmaxf(cnt, 1.0f);
        const float* sp = g_sums + ((size_t)h * MM + m) * DD;
        float s0 = sp[lane] * inv, s1 = sp[lane + 32] * inv;

        float dot = s0 * h0 + s1 * h1;
        float nl = s0 * s0 + s1 * s1;
        float nh = h0 * h0 + h1 * h1;
#pragma unroll
        for (int off = 16; off > 0; off >>= 1) {
            dot += __shfl_xor_sync(0xFFFFFFFFu, dot, off);
            nl  += __shfl_xor_sync(0xFFFFFFFFu, nl, off);
            nh  += __shfl_xor_sync(0xFFFFFFFFu, nh, off);
        }
        float c = dot / fmaxf(sqrtf(nl) * sqrtf(nh), COS_EPS);
        c = fminf(fmaxf(c, -1.0f + 1e-7f), 1.0f - 1e-7f);
        float om = acosf(c);
        float so = sinf(om);
        float wl = sinf(0.01f * om) / so;
        float wh = sinf(0.99f * om) / so;
        float r0 = s0 * wl + h0 * wh;
        float r1 = s1 * wl + h1 * wh;

        float ms = r0 * r0 + r1 * r1;
#pragma unroll
        for (int off = 16; off > 0; off >>= 1)
            ms += __shfl_xor_sync(0xFFFFFFFFu, ms, off);
        float rinv = rsqrtf(ms * (1.0f / 64.0f) + RMS_EPS);
        o0 = r0 * rinv;
        o1 = r1 * rinv;
    }

    size_t ob = OFF_CB + ((size_t)h * MM + m) * DD;
    out[ob + lane] = o0;
    out[ob + lane + 32] = o1;
}

// ---------------------------------------------------------------------------
extern "C" void kernel_launch(void* const* d_in, const int* in_sizes, int n_in,
                              void* d_out, int out_size) {
    const float* z  = (const float*)d_in[0];
    const float* cb = (const float*)d_in[1];
    float* out = (float*)d_out;

    cudaFuncSetAttribute(vq_gemm, cudaFuncAttributeMaxDynamicSharedMemorySize,
                         SM_TOTAL);

    vq_prep<<<2048, 256>>>(cb);
    vq_nop<<<1, 1>>>();
    vq_gemm<<<dim3(128, 8), 256, SM_TOTAL>>>(z, cb, out);
    vq_update<<<1024, 256>>>(cb, out);
}

// round 9
// speedup vs baseline: 1.4457x; 1.0785x over previous
#include <cuda_runtime.h>
#include <cuda_bf16.h>
#include <math.h>
#include <cstdint>

// ---------------- problem constants ----------------
#define HH 8
#define BB 8
#define LL 2048
#define MM 1024
#define DD 64
#define NPH 16384                         // tokens per head = BB*LL

// output layout (fp32, reference return order)
#define OFF_ZQ   0
#define N_ZQ     (8*512*2048)             // 8,388,608
#define OFF_LOSS (N_ZQ)
#define OFF_IDX  (N_ZQ + 1)
#define OFF_CB   (OFF_IDX + BB*HH*LL)

#define RMS_EPS  1.1920929e-07f
#define COS_EPS  1e-8f

// ---------------- device scratch (no allocs) ----------------
__device__ __align__(128) __nv_bfloat16 g_c1[HH*MM*DD];
__device__ __align__(128) __nv_bfloat16 g_c2[HH*MM*DD];
__device__ __align__(16) float g_sums[HH*MM*DD];
__device__ float g_counts[HH*MM];
__device__ float g_loss;

// ---------------- mma / ldmatrix / cp.async helpers ----------------
__device__ __forceinline__ void mma_bf16(float* d, const uint32_t* a,
                                         const uint32_t* b) {
    asm volatile(
        "mma.sync.aligned.m16n8k16.row.col.f32.bf16.bf16.f32 "
        "{%0,%1,%2,%3}, {%4,%5,%6,%7}, {%8,%9}, {%0,%1,%2,%3};"
        : "+f"(d[0]), "+f"(d[1]), "+f"(d[2]), "+f"(d[3])
        : "r"(a[0]), "r"(a[1]), "r"(a[2]), "r"(a[3]), "r"(b[0]), "r"(b[1]));
}
__device__ __forceinline__ void ldsm_x4(uint32_t& r0, uint32_t& r1,
                                        uint32_t& r2, uint32_t& r3,
                                        uint32_t addr) {
    asm volatile("ldmatrix.sync.aligned.m8n8.x4.shared.b16 {%0,%1,%2,%3}, [%4];"
                 : "=r"(r0), "=r"(r1), "=r"(r2), "=r"(r3) : "r"(addr));
}
__device__ __forceinline__ uint32_t smem_u32(const void* p) {
    uint32_t a;
    asm("{ .reg .u64 t; cvta.to.shared.u64 t, %1; cvt.u32.u64 %0, t; }"
        : "=r"(a) : "l"(p));
    return a;
}
#define CP16(dst, src) \
    asm volatile("cp.async.cg.shared.global [%0], [%1], 16;" \
                 :: "r"(dst), "l"(src))
#define CP_COMMIT() asm volatile("cp.async.commit_group;" ::: "memory")
#define CP_WAIT(n)  asm volatile("cp.async.wait_group %0;" :: "n"(n) : "memory")

// ---------------- split fp32 -> 2 bf16 terms ----------------
__device__ __forceinline__ void split2(float v, __nv_bfloat16& a,
                                       __nv_bfloat16& b) {
    a = __float2bfloat16(v);
    b = __float2bfloat16(v - __bfloat162float(a));
}
__device__ __forceinline__ uint32_t pack2(__nv_bfloat16 lo, __nv_bfloat16 hi) {
    __nv_bfloat162 t;
    t.x = lo; t.y = hi;
    return *(uint32_t*)&t;
}

// top-2 helpers
__device__ __forceinline__ void upd2(float& b1, int& i1, float& b2, int& i2,
                                     float v, int idx) {
    if (v > b1) { b2 = b1; i2 = i1; b1 = v; i1 = idx; }
    else if (v > b2) { b2 = v; i2 = idx; }
}
__device__ __forceinline__ bool better(float av, int ai, float bv, int bi) {
    return av > bv || (av == bv && ai < bi);
}
__device__ __forceinline__ void merge2(float& b1, int& i1, float& b2, int& i2,
                                       float o1, int oi1, float o2, int oi2) {
    if (better(o1, oi1, b1, i1)) {
        if (better(b1, i1, o2, oi2)) { b2 = b1; i2 = i1; }
        else { b2 = o2; i2 = oi2; }
        b1 = o1; i1 = oi1;
    } else if (better(o1, oi1, b2, i2)) {
        b2 = o1; i2 = oi1;
    }
}

// ---------------------------------------------------------------------------
// K0: prep — split codebooks to 2 bf16 terms; zero scratch
// ---------------------------------------------------------------------------
__global__ __launch_bounds__(256)
void vq_prep(const float* __restrict__ cb) {
    int i = blockIdx.x * 256 + threadIdx.x;   // < 524288
    float v = cb[i];
    __nv_bfloat16 a, b;
    split2(v, a, b);
    g_c1[i] = a; g_c2[i] = b;
    g_sums[i] = 0.0f;
    if (i < HH * MM) g_counts[i] = 0.0f;
    if (i == 0) g_loss = 0.0f;
}

// ---------------------------------------------------------------------------
// K1: fused — z stage + split + 3-pair HMMA phase-1 + top-2 + exact rescore
//     + coalesced epilogue. CTA = (head, 128 tokens). 8 warps, 16 rows each.
// ---------------------------------------------------------------------------
#define BPITCH 144
#define BT64   (64 * BPITCH)              // 9216 B per term per stage
#define BSTAGE (2 * BT64)                 // 18432 B per stage (2 terms)
#define ZPITCH 132
#define ZQPITCH 129
#define SM_Z     (2 * BSTAGE)             // 36864 (zq staging reuses [0,36864))
#define SM_CANDS (SM_Z + 64 * ZPITCH * 4) // 70656
#define SM_SIDX  (SM_CANDS + 1024)        // 71680
#define SM_WSUM  (SM_SIDX + 512)          // 72192
#define SM_TOTAL (SM_WSUM + 32)           // 72224  -> 2 CTAs/SM

__global__ __launch_bounds__(256, 2)
void vq_gemm(const float* __restrict__ z, const float* __restrict__ cb,
             float* __restrict__ out) {
    extern __shared__ char smem[];
    float* zsh = (float*)(smem + SM_Z);
    int2* cands = (int2*)(smem + SM_CANDS);
    int* sidx = (int*)(smem + SM_SIDX);
    float* wsum = (float*)(smem + SM_WSUM);
    const uint32_t sb = smem_u32(smem);

    const int h  = blockIdx.y;
    const int n0 = blockIdx.x * 128;
    const int b  = n0 >> 11;              // batch
    const int l0 = n0 & 2047;             // l offset within batch
    const int tid = threadIdx.x;
    const int w = tid >> 5, l = tid & 31;
    const int gq = l >> 2, tq = l & 3;

    // ---- prologue: cp.async z tile (group Z), then B tile 0 (group 0) ----
    const float* zb = z + ((size_t)b * 512 + (size_t)h * 64) * 2048 + l0;
    for (int i = tid; i < 64 * 32; i += 256) {
        int k = i >> 5, c = i & 31;
        CP16(sb + SM_Z + (k * ZPITCH + c * 4) * 4,
             (const char*)(zb + (size_t)k * 2048 + c * 4));
    }
    CP_COMMIT();
    for (int j = tid; j < 1024; j += 256) {     // B tile 0 -> stage 0
        int t3 = j >> 9, rr = (j >> 3) & 63, c = j & 7;
        const __nv_bfloat16* cp = t3 ? g_c2 : g_c1;
        CP16(sb + t3 * BT64 + rr * BPITCH + c * 16,
             (const char*)(cp + ((size_t)h * MM + rr) * DD) + c * 16);
    }
    CP_COMMIT();

    CP_WAIT(1);              // z ready (B tile 0 may still be in flight)
    __syncthreads();

    // ---- build A fragments in regs: 2 terms x 4 ksteps x 4 regs ----
    uint32_t afr[2][4][4];
    {
        const int r0 = w * 16 + gq;
#pragma unroll
        for (int ks = 0; ks < 4; ks++)
#pragma unroll
            for (int half = 0; half < 2; half++)
#pragma unroll
                for (int rr = 0; rr < 2; rr++) {
                    int k0 = ks * 16 + 2 * tq + half * 8;
                    int row = r0 + rr * 8;
                    float v0 = zsh[k0 * ZPITCH + row];
                    float v1 = zsh[(k0 + 1) * ZPITCH + row];
                    __nv_bfloat16 a0, b0, a1, b1;
                    split2(v0, a0, b0);
                    split2(v1, a1, b1);
                    int reg = rr + half * 2;
                    afr[0][ks][reg] = pack2(a0, a1);
                    afr[1][ks][reg] = pack2(b0, b1);
                }
    }

    // per-thread top-2 for the two row outputs (row rl and rl+8)
    float b0a = -3.0e38f, b0b = -3.0e38f, b1a = -3.0e38f, b1b = -3.0e38f;
    int   i0a = 0, i0b = 1, i1a = 0, i1b = 1;

    const uint32_t laneoff = (((l >> 4) * 8 + (l & 7)) * BPITCH) +
                             (((l >> 3) & 1) * 16);

    for (int mt = 0; mt < 16; mt++) {
        CP_WAIT(0);                        // tile mt resident in stage mt&1
        __syncthreads();

        if (mt < 15) {                     // prefetch tile mt+1 into other stage
            uint32_t dstb = sb + ((mt + 1) & 1) * BSTAGE;
            for (int j = tid; j < 1024; j += 256) {
                int t3 = j >> 9, rr = (j >> 3) & 63, c = j & 7;
                const __nv_bfloat16* cp = t3 ? g_c2 : g_c1;
                CP16(dstb + t3 * BT64 + rr * BPITCH + c * 16,
                     (const char*)(cp + ((size_t)h * MM + (mt + 1) * 64 + rr) * DD)
                         + c * 16);
            }
            CP_COMMIT();
        }

        const uint32_t bbase = sb + (mt & 1) * BSTAGE + laneoff;

#pragma unroll
        for (int sg = 0; sg < 2; sg++) {
            float acc[4][4];
#pragma unroll
            for (int s = 0; s < 4; s++)
#pragma unroll
                for (int i = 0; i < 4; i++) acc[s][i] = 0.0f;

#pragma unroll
            for (int ks = 0; ks < 4; ks++) {
                uint32_t bfr[2][4][2];
#pragma unroll
                for (int t3 = 0; t3 < 2; t3++)
#pragma unroll
                    for (int sp = 0; sp < 2; sp++) {
                        uint32_t addr = bbase + t3 * BT64 +
                                        (sg * 32 + sp * 16) * BPITCH + ks * 32;
                        ldsm_x4(bfr[t3][sp * 2][0], bfr[t3][sp * 2][1],
                                bfr[t3][sp * 2 + 1][0], bfr[t3][sp * 2 + 1][1],
                                addr);
                    }
                // 3 pairs: (z1,c1), (z1,c2), (z2,c1)
#pragma unroll
                for (int s = 0; s < 4; s++) {
                    mma_bf16(acc[s], afr[0][ks], bfr[0][s]);
                    mma_bf16(acc[s], afr[0][ks], bfr[1][s]);
                    mma_bf16(acc[s], afr[1][ks], bfr[0][s]);
                }
            }

            // top-2 update (ascending index scan, strict > keeps lowest)
#pragma unroll
            for (int s = 0; s < 4; s++) {
                int nb = mt * 64 + sg * 32 + s * 8 + 2 * tq;
                upd2(b0a, i0a, b0b, i0b, acc[s][0], nb);
                upd2(b0a, i0a, b0b, i0b, acc[s][1], nb + 1);
                upd2(b1a, i1a, b1b, i1b, acc[s][2], nb);
                upd2(b1a, i1a, b1b, i1b, acc[s][3], nb + 1);
            }
        }
    }

    // ---- merge top-2 across the 4 lanes covering each row ----
#pragma unroll
    for (int off = 1; off <= 2; off <<= 1) {
        float o1 = __shfl_xor_sync(0xFFFFFFFFu, b0a, off);
        int   q1 = __shfl_xor_sync(0xFFFFFFFFu, i0a, off);
        float o2 = __shfl_xor_sync(0xFFFFFFFFu, b0b, off);
        int   q2 = __shfl_xor_sync(0xFFFFFFFFu, i0b, off);
        merge2(b0a, i0a, b0b, i0b, o1, q1, o2, q2);
        o1 = __shfl_xor_sync(0xFFFFFFFFu, b1a, off);
        q1 = __shfl_xor_sync(0xFFFFFFFFu, i1a, off);
        o2 = __shfl_xor_sync(0xFFFFFFFFu, b1b, off);
        q2 = __shfl_xor_sync(0xFFFFFFFFu, i1b, off);
        merge2(b1a, i1a, b1b, i1b, o1, q1, o2, q2);
    }

    if (tq == 0) {
        int rl = w * 16 + gq;
        cands[rl] = make_int2(i0a, i0b);
        cands[rl + 8] = make_int2(i1a, i1b);
    }
    __syncthreads();

    // ---- exact fp32 rescore of the 2 candidates per row ----
    const float* cbh = cb + (size_t)h * MM * DD;
    {
        int row = tid >> 1, c = tid & 1;
        int2 cc = cands[row];
        int m = c ? cc.y : cc.x;
        const float4* cr = (const float4*)(cbh + (size_t)m * DD);
        float dot = 0.0f;
#pragma unroll
        for (int k4 = 0; k4 < 16; k4++) {
            float4 cv = __ldg(cr + k4);
            dot += zsh[(4 * k4) * ZPITCH + row] * cv.x;
            dot += zsh[(4 * k4 + 1) * ZPITCH + row] * cv.y;
            dot += zsh[(4 * k4 + 2) * ZPITCH + row] * cv.z;
            dot += zsh[(4 * k4 + 3) * ZPITCH + row] * cv.w;
        }
        float od = __shfl_xor_sync(0xFFFFFFFFu, dot, 1);
        int   om = __shfl_xor_sync(0xFFFFFFFFu, m, 1);
        if (c == 0) {
            int win = better(dot, m, od, om) ? m : om;
            sidx[row] = win;
            out[OFF_IDX + ((size_t)(b * HH + h)) * LL + l0 + row] = (float)win;
            atomicAdd(&g_counts[h * MM + win], 1.0f);
        }
    }
    __syncthreads();

    // ---- epilogue phase A: coalesced cb gather -> smem zq stage + loss ----
    float* zqs = (float*)smem;                   // reuse dead B stages (33 KB)
    float lsum = 0.0f;
    for (int i = tid; i < 128 * 16; i += 256) {
        int ll = i >> 4, kg = i & 15;            // 16 threads cover one cb row
        int m = sidx[ll];
        float4 cv = __ldg((const float4*)(cbh + (size_t)m * DD + 4 * kg));
        zqs[(4 * kg) * ZQPITCH + ll] = cv.x;
        zqs[(4 * kg + 1) * ZQPITCH + ll] = cv.y;
        zqs[(4 * kg + 2) * ZQPITCH + ll] = cv.z;
        zqs[(4 * kg + 3) * ZQPITCH + ll] = cv.w;
        float d0 = zsh[(4 * kg) * ZPITCH + ll] - cv.x;
        float d1 = zsh[(4 * kg + 1) * ZPITCH + ll] - cv.y;
        float d2 = zsh[(4 * kg + 2) * ZPITCH + ll] - cv.z;
        float d3 = zsh[(4 * kg + 3) * ZPITCH + ll] - cv.w;
        lsum += d0 * d0 + d1 * d1 + d2 * d2 + d3 * d3;
    }

    // segment sums: thread = (ll, 4k-group) -> float4 atomic
    for (int i = tid; i < 128 * 16; i += 256) {
        int ll = i >> 4, kg = i & 15;
        int m = sidx[ll];
        float4 v = make_float4(zsh[(4 * kg) * ZPITCH + ll],
                               zsh[(4 * kg + 1) * ZPITCH + ll],
                               zsh[(4 * kg + 2) * ZPITCH + ll],
                               zsh[(4 * kg + 3) * ZPITCH + ll]);
        atomicAdd((float4*)&g_sums[((size_t)(h * MM + m)) * DD + 4 * kg], v);
    }
    __syncthreads();

    // ---- epilogue phase B: coalesced zq write ----
    float* zqb = out + OFF_ZQ + ((size_t)b * 512 + (size_t)h * 64) * 2048 + l0;
    for (int i = tid; i < 64 * 128; i += 256) {
        int k = i >> 7, ll = i & 127;
        zqb[(size_t)k * 2048 + ll] = zqs[k * ZQPITCH + ll];
    }

    // loss reduce
#pragma unroll
    for (int off = 16; off > 0; off >>= 1)
        lsum += __shfl_xor_sync(0xFFFFFFFFu, lsum, off);
    if (l == 0) wsum[w] = lsum;
    __syncthreads();
    if (tid == 0) {
        float s = 0.0f;
#pragma unroll
        for (int ww = 0; ww < 8; ww++) s += wsum[ww];
        atomicAdd(&g_loss, s);
    }
}

// ---------------------------------------------------------------------------
// K2: EMA slerp codebook update + loss finalize. One warp per (h, m).
// ---------------------------------------------------------------------------
__global__ __launch_bounds__(256)
void vq_update(const float* __restrict__ cb, float* __restrict__ out) {
    int gid = blockIdx.x * blockDim.x + threadIdx.x;
    int gw = gid >> 5;
    int lane = threadIdx.x & 31;

    if (gw == 0 && lane == 0)
        out[OFF_LOSS] = 1.25f * g_loss / 8388608.0f;

    if (gw >= HH * MM) return;
    int h = gw >> 10;
    int m = gw & (MM - 1);

    const float* hi = cb + ((size_t)h * MM + m) * DD;
    float h0 = hi[lane], h1 = hi[lane + 32];
    float cnt = g_counts[h * MM + m];
    float o0 = h0, o1 = h1;

    if (cnt > 0.0f) {
        float inv = 1.0f / fmaxf(cnt, 1.0f);
        const float* sp = g_sums + ((size_t)h * MM + m) * DD;
        float s0 = sp[lane] * inv, s1 = sp[lane + 32] * inv;

        float dot = s0 * h0 + s1 * h1;
        float nl = s0 * s0 + s1 * s1;
        float nh = h0 * h0 + h1 * h1;
#pragma unroll
        for (int off = 16; off > 0; off >>= 1) {
            dot += __shfl_xor_sync(0xFFFFFFFFu, dot, off);
            nl  += __shfl_xor_sync(0xFFFFFFFFu, nl, off);
            nh  += __shfl_xor_sync(0xFFFFFFFFu, nh, off);
        }
        float c = dot / fmaxf(sqrtf(nl) * sqrtf(nh), COS_EPS);
        c = fminf(fmaxf(c, -1.0f + 1e-7f), 1.0f - 1e-7f);
        float om = acosf(c);
        float so = sinf(om);
        float wl = sinf(0.01f * om) / so;
        float wh = sinf(0.99f * om) / so;
        float r0 = s0 * wl + h0 * wh;
        float r1 = s1 * wl + h1 * wh;

        float ms = r0 * r0 + r1 * r1;
#pragma unroll
        for (int off = 16; off > 0; off >>= 1)
            ms += __shfl_xor_sync(0xFFFFFFFFu, ms, off);
        float rinv = rsqrtf(ms * (1.0f / 64.0f) + RMS_EPS);
        o0 = r0 * rinv;
        o1 = r1 * rinv;
    }

    size_t ob = OFF_CB + ((size_t)h * MM + m) * DD;
    out[ob + lane] = o0;
    out[ob + lane + 32] = o1;
}

// ---------------------------------------------------------------------------
extern "C" void kernel_launch(void* const* d_in, const int* in_sizes, int n_in,
                              void* d_out, int out_size) {
    const float* z  = (const float*)d_in[0];
    const float* cb = (const float*)d_in[1];
    float* out = (float*)d_out;

    cudaFuncSetAttribute(vq_gemm, cudaFuncAttributeMaxDynamicSharedMemorySize,
                         SM_TOTAL);

    vq_prep<<<2048, 256>>>(cb);
    vq_gemm<<<dim3(128, 8), 256, SM_TOTAL>>>(z, cb, out);
    vq_update<<<1024, 256>>>(cb, out);
}